// round 1
// baseline (speedup 1.0000x reference)
#include <cuda_runtime.h>

#define N_MAX   1000000
#define D       32
#define HID     16
#define NB      592          // grid for kernel 1
#define T1      128          // threads for kernel 1

// ---------------- scratch (no allocations allowed) ----------------
__device__ float g_a[N_MAX];          // per-row raw attention logits
__device__ float g_bmax[NB];
__device__ float g_bsum[NB];
__device__ float g_bB[NB * D];
__device__ float g_stats[2];          // [0]=global max, [1]=1/S

// ---------------- packed f32x2 helpers ----------------
__device__ __forceinline__ unsigned long long pack2(float lo, float hi) {
    unsigned long long r;
    asm("mov.b64 %0, {%1, %2};" : "=l"(r) : "f"(lo), "f"(hi));
    return r;
}
__device__ __forceinline__ void unpack2(unsigned long long v, float& lo, float& hi) {
    asm("mov.b64 {%0, %1}, %2;" : "=f"(lo), "=f"(hi) : "l"(v));
}
__device__ __forceinline__ void fma2(unsigned long long& d,
                                     unsigned long long a, unsigned long long b) {
    asm("fma.rn.f32x2 %0, %1, %2, %3;" : "=l"(d) : "l"(a), "l"(b), "l"(d));
}
__device__ __forceinline__ unsigned long long mul2(unsigned long long a,
                                                   unsigned long long b) {
    unsigned long long r;
    asm("mul.rn.f32x2 %0, %1, %2;" : "=l"(r) : "l"(a), "l"(b));
    return r;
}
__device__ __forceinline__ float fast_tanh(float x) {
    float r;
    asm("tanh.approx.f32 %0, %1;" : "=f"(r) : "f"(x));
    return r;
}

// =====================================================================
// Kernel 1: per-row logits + online (max, sumexp, weighted-H) per block
// =====================================================================
__global__ void __launch_bounds__(T1)
k1_logits(const float4* __restrict__ H4, int n,
          const float* __restrict__ Wv, const float* __restrict__ bv,
          const float* __restrict__ Wu, const float* __restrict__ bu,
          const float* __restrict__ Ww, const float* __restrict__ bw)
{
    __shared__ __align__(16) float swv[D * HID];   // Wv[d][h], h-contiguous
    __shared__ __align__(16) float swu[D * HID];
    __shared__ float sbv[HID], sbu[HID], sWw[HID];
    __shared__ float red_m[T1], red_s[T1];
    __shared__ float red_B[T1][D];                 // 16 KB

    const int t = threadIdx.x;
    for (int i = t; i < D * HID; i += T1) { swv[i] = Wv[i]; swu[i] = Wu[i]; }
    if (t < HID) { sbv[t] = bv[t]; sbu[t] = bu[t]; sWw[t] = Ww[t]; }
    __syncthreads();

    const float bw0 = bw[0];

    float m = -1e30f, s = 0.0f;
    unsigned long long B[D / 2];                   // packed over d-pairs
    #pragma unroll
    for (int k = 0; k < D / 2; k++) B[k] = 0ULL;   // bits of (0.f,0.f)

    for (int r = blockIdx.x * T1 + t; r < n; r += NB * T1) {
        // ---- load full row (32 floats = 8 float4, high MLP) ----
        float4 x[8];
        const float4* p = H4 + (size_t)r * 8;
        #pragma unroll
        for (int c = 0; c < 8; c++) x[c] = p[c];

        // ---- v/u accumulators packed over hidden pairs ----
        unsigned long long v[HID / 2], u[HID / 2];
        #pragma unroll
        for (int k = 0; k < HID / 2; k++) { v[k] = 0ULL; u[k] = 0ULL; }

        #pragma unroll
        for (int c = 0; c < 8; c++) {
            float xv[4] = {x[c].x, x[c].y, x[c].z, x[c].w};
            #pragma unroll
            for (int j = 0; j < 4; j++) {
                const int d = c * 4 + j;
                const unsigned long long hd = pack2(xv[j], xv[j]);
                const ulonglong2* wv2 = (const ulonglong2*)(swv + d * HID);
                const ulonglong2* wu2 = (const ulonglong2*)(swu + d * HID);
                #pragma unroll
                for (int k = 0; k < 4; k++) {      // 16 weights = 4 LDS.128
                    ulonglong2 w = wv2[k];
                    fma2(v[2 * k], hd, w.x);
                    fma2(v[2 * k + 1], hd, w.y);
                }
                #pragma unroll
                for (int k = 0; k < 4; k++) {
                    ulonglong2 w = wu2[k];
                    fma2(u[2 * k], hd, w.x);
                    fma2(u[2 * k + 1], hd, w.y);
                }
            }
        }

        // ---- epilogue: a = bw + sum_h Ww[h] * tanh(v_h+bv) * sigmoid(u_h+bu)
        float a = bw0;
        #pragma unroll
        for (int k = 0; k < HID / 2; k++) {
            float v0, v1, u0, u1;
            unpack2(v[k], v0, v1);
            unpack2(u[k], u0, u1);
            const int h0 = 2 * k, h1 = 2 * k + 1;
            float t0 = fast_tanh(v0 + sbv[h0]);
            float t1 = fast_tanh(v1 + sbv[h1]);
            float s0 = fmaf(0.5f, fast_tanh(0.5f * (u0 + sbu[h0])), 0.5f);
            float s1 = fmaf(0.5f, fast_tanh(0.5f * (u1 + sbu[h1])), 0.5f);
            a = fmaf(sWw[h0] * t0, s0, a);
            a = fmaf(sWw[h1] * t1, s1, a);
        }
        g_a[r] = a;

        // ---- online softmax + weighted-H accumulation (row still in regs)
        float mn = fmaxf(m, a);
        if (mn > m) {
            float c0 = __expf(m - mn);
            s *= c0;
            unsigned long long cc = pack2(c0, c0);
            #pragma unroll
            for (int k = 0; k < D / 2; k++) B[k] = mul2(B[k], cc);
        }
        m = mn;
        float e = __expf(a - m);
        s += e;
        unsigned long long ee = pack2(e, e);
        #pragma unroll
        for (int c = 0; c < 8; c++) {
            fma2(B[2 * c],     ee, pack2(x[c].x, x[c].y));
            fma2(B[2 * c + 1], ee, pack2(x[c].z, x[c].w));
        }
    }

    // ---- block reduction of (m, s, B) with exp rescaling ----
    red_m[t] = m; red_s[t] = s;
    #pragma unroll
    for (int k = 0; k < D / 2; k++) {
        float lo, hi;
        unpack2(B[k], lo, hi);
        red_B[t][2 * k] = lo; red_B[t][2 * k + 1] = hi;
    }
    for (int stride = T1 / 2; stride >= 1; stride >>= 1) {
        __syncthreads();
        if (t < stride) {
            float m1 = red_m[t], s1 = red_s[t];
            float m2 = red_m[t + stride], s2 = red_s[t + stride];
            float mn = fmaxf(m1, m2);
            float c1 = __expf(m1 - mn), c2 = __expf(m2 - mn);
            red_m[t] = mn;
            red_s[t] = s1 * c1 + s2 * c2;
            for (int d = 0; d < D; d++)
                red_B[t][d] = red_B[t][d] * c1 + red_B[t + stride][d] * c2;
        }
    }
    __syncthreads();
    if (t == 0) { g_bmax[blockIdx.x] = red_m[0]; g_bsum[blockIdx.x] = red_s[0]; }
    if (t < D)  g_bB[blockIdx.x * D + t] = red_B[0][t];
}

// =====================================================================
// Kernel 2: combine block stats, compute score head, stash (max, 1/S)
// =====================================================================
__global__ void k2_combine(const float* __restrict__ TPL,
                           const float* __restrict__ W1, const float* __restrict__ b1,
                           const float* __restrict__ W2, const float* __restrict__ b2,
                           float* __restrict__ out_score)
{
    __shared__ float sm[128], ss[128];
    __shared__ float Bbar[D];
    __shared__ float hsh[HID];
    const int t = threadIdx.x;

    float m = -1e30f;
    for (int b = t; b < NB; b += 128) m = fmaxf(m, g_bmax[b]);
    sm[t] = m;
    __syncthreads();
    for (int st = 64; st >= 1; st >>= 1) {
        if (t < st) sm[t] = fmaxf(sm[t], sm[t + st]);
        __syncthreads();
    }
    const float gm = sm[0];

    float s = 0.0f;
    for (int b = t; b < NB; b += 128) s += g_bsum[b] * __expf(g_bmax[b] - gm);
    ss[t] = s;
    __syncthreads();
    for (int st = 64; st >= 1; st >>= 1) {
        if (t < st) ss[t] += ss[t + st];
        __syncthreads();
    }
    const float S = ss[0];

    if (t < D) {
        float acc = 0.0f;
        for (int b = 0; b < NB; b++) acc += g_bB[b * D + t] * __expf(g_bmax[b] - gm);
        Bbar[t] = acc / S;
    }
    if (t == 0) { g_stats[0] = gm; g_stats[1] = 1.0f / S; }
    __syncthreads();

    if (t < HID) {
        float acc = b1[t] + TPL[0] * W1[D * HID + t];   // W1 row 32 = TPL row
        for (int d = 0; d < D; d++) acc = fmaf(Bbar[d], W1[d * HID + t], acc);
        hsh[t] = fmaxf(acc, 0.0f);
    }
    __syncthreads();
    if (t == 0) {
        float sc = b2[0];
        for (int j = 0; j < HID; j++) sc = fmaf(hsh[j], W2[j], sc);
        out_score[0] = sc;
    }
}

// =====================================================================
// Kernel 3: alpha_i = exp(a_i - gm) / S
// =====================================================================
__global__ void k3_alpha(float* __restrict__ alpha, int n)
{
    const float gm = g_stats[0], inv = g_stats[1];
    int i = blockIdx.x * blockDim.x + threadIdx.x;
    if (i < n) alpha[i] = __expf(g_a[i] - gm) * inv;
}

// =====================================================================
// Inputs (metadata order): H, TPL, Wv, bv, Wu, bu, Ww, bw, W1, b1, W2, b2
// Output: [score, alpha[0..N-1]]
// =====================================================================
extern "C" void kernel_launch(void* const* d_in, const int* in_sizes, int n_in,
                              void* d_out, int out_size)
{
    const float* H   = (const float*)d_in[0];
    const float* TPL = (const float*)d_in[1];
    const float* Wv  = (const float*)d_in[2];
    const float* bv  = (const float*)d_in[3];
    const float* Wu  = (const float*)d_in[4];
    const float* bu  = (const float*)d_in[5];
    const float* Ww  = (const float*)d_in[6];
    const float* bw  = (const float*)d_in[7];
    const float* W1  = (const float*)d_in[8];
    const float* b1  = (const float*)d_in[9];
    const float* W2  = (const float*)d_in[10];
    const float* b2  = (const float*)d_in[11];
    float* out = (float*)d_out;

    const int n = in_sizes[0] / D;   // 1,000,000

    k1_logits<<<NB, T1>>>((const float4*)H, n, Wv, bv, Wu, bu, Ww, bw);
    k2_combine<<<1, 128>>>(TPL, W1, b1, W2, b2, out);
    k3_alpha<<<(n + 255) / 256, 256>>>(out + 1, n);
}

// round 2
// speedup vs baseline: 1.0095x; 1.0095x over previous
#include <cuda_runtime.h>

#define N_MAX   1000000
#define D       32
#define HID     16
#define NB      592          // grid for K1/K3 (148 SMs x 4 blocks)
#define T1      128

// ---------------- scratch (no allocations allowed) ----------------
__device__ float g_a[N_MAX];          // per-row raw attention logits
__device__ float g_bm[NB];            // per-block running max
__device__ float g_bs[NB];            // per-block running sumexp
__device__ float g_bB[NB * D];        // per-block partial alpha-weighted H
__device__ float g_stats[2];          // [0]=global max, [1]=1/S

// ---------------- packed f32x2 helpers ----------------
__device__ __forceinline__ unsigned long long pack2(float lo, float hi) {
    unsigned long long r;
    asm("mov.b64 %0, {%1, %2};" : "=l"(r) : "f"(lo), "f"(hi));
    return r;
}
__device__ __forceinline__ void unpack2(unsigned long long v, float& lo, float& hi) {
    asm("mov.b64 {%0, %1}, %2;" : "=f"(lo), "=f"(hi) : "l"(v));
}
__device__ __forceinline__ void fma2(unsigned long long& d,
                                     unsigned long long a, unsigned long long b) {
    asm("fma.rn.f32x2 %0, %1, %2, %3;" : "=l"(d) : "l"(a), "l"(b), "l"(d));
}
__device__ __forceinline__ float fast_tanh(float x) {
    float r;
    asm("tanh.approx.f32 %0, %1;" : "=f"(r) : "f"(x));
    return r;
}

// =====================================================================
// K1: per-row logits + per-block online (max, sumexp).  NO B here
//     (keeping B in registers caused 255-reg spill catastrophe in R1).
// =====================================================================
__global__ void __launch_bounds__(T1, 4)
k1_logits(const float4* __restrict__ H4, int n,
          const float* __restrict__ Wv, const float* __restrict__ bv,
          const float* __restrict__ Wu, const float* __restrict__ bu,
          const float* __restrict__ Ww, const float* __restrict__ bw)
{
    __shared__ __align__(16) float swv[D * HID];   // Wv[d][h], h-contiguous
    __shared__ __align__(16) float swu[D * HID];
    __shared__ float sbv[HID], sbu[HID], sWw[HID];
    __shared__ float red_m[T1], red_s[T1];

    const int t = threadIdx.x;
    for (int i = t; i < D * HID; i += T1) { swv[i] = Wv[i]; swu[i] = Wu[i]; }
    if (t < HID) { sbv[t] = bv[t]; sbu[t] = bu[t]; sWw[t] = Ww[t]; }
    __syncthreads();

    const float bw0 = bw[0];

    float m = -1e30f, s = 0.0f;

    for (int r = blockIdx.x * T1 + t; r < n; r += NB * T1) {
        float4 x[8];
        const float4* p = H4 + (size_t)r * 8;
        #pragma unroll
        for (int c = 0; c < 8; c++) x[c] = p[c];

        unsigned long long v[HID / 2], u[HID / 2];
        #pragma unroll
        for (int k = 0; k < HID / 2; k++) { v[k] = 0ULL; u[k] = 0ULL; }

        #pragma unroll
        for (int c = 0; c < 8; c++) {
            float xv[4] = {x[c].x, x[c].y, x[c].z, x[c].w};
            #pragma unroll
            for (int j = 0; j < 4; j++) {
                const int d = c * 4 + j;
                const unsigned long long hd = pack2(xv[j], xv[j]);
                const ulonglong2* wv2 = (const ulonglong2*)(swv + d * HID);
                const ulonglong2* wu2 = (const ulonglong2*)(swu + d * HID);
                #pragma unroll
                for (int k = 0; k < 4; k++) {
                    ulonglong2 w = wv2[k];
                    fma2(v[2 * k], hd, w.x);
                    fma2(v[2 * k + 1], hd, w.y);
                }
                #pragma unroll
                for (int k = 0; k < 4; k++) {
                    ulonglong2 w = wu2[k];
                    fma2(u[2 * k], hd, w.x);
                    fma2(u[2 * k + 1], hd, w.y);
                }
            }
        }

        float a = bw0;
        #pragma unroll
        for (int k = 0; k < HID / 2; k++) {
            float v0, v1, u0, u1;
            unpack2(v[k], v0, v1);
            unpack2(u[k], u0, u1);
            const int h0 = 2 * k, h1 = 2 * k + 1;
            float t0 = fast_tanh(v0 + sbv[h0]);
            float t1 = fast_tanh(v1 + sbv[h1]);
            float s0 = fmaf(0.5f, fast_tanh(0.5f * (u0 + sbu[h0])), 0.5f);
            float s1 = fmaf(0.5f, fast_tanh(0.5f * (u1 + sbu[h1])), 0.5f);
            a = fmaf(sWw[h0] * t0, s0, a);
            a = fmaf(sWw[h1] * t1, s1, a);
        }
        g_a[r] = a;

        // online (max, sumexp) — scalars only, branchless
        float mn = fmaxf(m, a);
        s = fmaf(s, __expf(m - mn), __expf(a - mn));
        m = mn;
    }

    // block reduction of (m, s)
    red_m[t] = m; red_s[t] = s;
    for (int stride = T1 / 2; stride >= 1; stride >>= 1) {
        __syncthreads();
        if (t < stride) {
            float m1 = red_m[t], s1 = red_s[t];
            float m2 = red_m[t + stride], s2 = red_s[t + stride];
            float mn = fmaxf(m1, m2);
            red_m[t] = mn;
            red_s[t] = fmaf(s1, __expf(m1 - mn), s2 * __expf(m2 - mn));
        }
    }
    __syncthreads();
    if (t == 0) { g_bm[blockIdx.x] = red_m[0]; g_bs[blockIdx.x] = red_s[0]; }
}

// =====================================================================
// K2: combine per-block (max, sumexp) -> global max, 1/S
// =====================================================================
__global__ void k2_stats()
{
    __shared__ float sm[256], ss[256];
    const int t = threadIdx.x;

    float m = -1e30f, s = 0.0f;
    for (int b = t; b < NB; b += 256) {
        float mb = g_bm[b], sb = g_bs[b];
        float mn = fmaxf(m, mb);
        s = fmaf(s, __expf(m - mn), sb * __expf(mb - mn));
        m = mn;
    }
    sm[t] = m; ss[t] = s;
    for (int stride = 128; stride >= 1; stride >>= 1) {
        __syncthreads();
        if (t < stride) {
            float m1 = sm[t], s1 = ss[t];
            float m2 = sm[t + stride], s2 = ss[t + stride];
            float mn = fmaxf(m1, m2);
            sm[t] = mn;
            ss[t] = fmaf(s1, __expf(m1 - mn), s2 * __expf(m2 - mn));
        }
    }
    __syncthreads();
    if (t == 0) { g_stats[0] = sm[0]; g_stats[1] = 1.0f / ss[0]; }
}

// =====================================================================
// K3: alpha_i = exp(a_i - gm) * invS  (written to output),
//     plus per-block partial B = sum_i alpha_i * H_i
// =====================================================================
__global__ void __launch_bounds__(T1, 4)
k3_alpha_B(const float4* __restrict__ H4, int n, float* __restrict__ alpha)
{
    __shared__ float redB[T1][D];   // 16 KB
    const int t = threadIdx.x;
    const float gm = g_stats[0], invS = g_stats[1];

    unsigned long long B[D / 2];
    #pragma unroll
    for (int k = 0; k < D / 2; k++) B[k] = 0ULL;

    for (int r = blockIdx.x * T1 + t; r < n; r += NB * T1) {
        float4 x[8];
        const float4* p = H4 + (size_t)r * 8;
        #pragma unroll
        for (int c = 0; c < 8; c++) x[c] = p[c];

        float e = __expf(g_a[r] - gm) * invS;
        alpha[r] = e;

        const unsigned long long ee = pack2(e, e);
        #pragma unroll
        for (int c = 0; c < 8; c++) {
            fma2(B[2 * c],     ee, pack2(x[c].x, x[c].y));
            fma2(B[2 * c + 1], ee, pack2(x[c].z, x[c].w));
        }
    }

    #pragma unroll
    for (int k = 0; k < D / 2; k++) {
        float lo, hi;
        unpack2(B[k], lo, hi);
        redB[t][2 * k] = lo; redB[t][2 * k + 1] = hi;
    }
    __syncthreads();
    // threads 0..31 each own one d-column; fixed order (deterministic)
    if (t < D) {
        float acc = 0.0f;
        #pragma unroll 8
        for (int i = 0; i < T1; i++) acc += redB[i][t];
        g_bB[blockIdx.x * D + t] = acc;
    }
}

// =====================================================================
// K4: reduce partial B over blocks (alpha already normalized, so this
//     is Bbar directly), then the tiny score head.
// =====================================================================
__global__ void __launch_bounds__(1024)
k4_head(const float* __restrict__ TPL,
        const float* __restrict__ W1, const float* __restrict__ b1,
        const float* __restrict__ W2, const float* __restrict__ b2,
        float* __restrict__ out_score)
{
    __shared__ float part[32][D + 1];
    __shared__ float Bbar[D];
    __shared__ float hsh[HID];
    const int t = threadIdx.x;
    const int d = t & (D - 1);
    const int g = t >> 5;           // 32 groups

    float acc = 0.0f;
    for (int b = g; b < NB; b += 32) acc += g_bB[b * D + d];
    part[g][d] = acc;
    __syncthreads();

    if (t < D) {
        float a2 = 0.0f;
        #pragma unroll
        for (int i = 0; i < 32; i++) a2 += part[i][t];
        Bbar[t] = a2;
    }
    __syncthreads();

    if (t < HID) {
        float a3 = b1[t] + TPL[0] * W1[D * HID + t];   // W1 row 32 = TPL row
        #pragma unroll
        for (int dd = 0; dd < D; dd++) a3 = fmaf(Bbar[dd], W1[dd * HID + t], a3);
        hsh[t] = fmaxf(a3, 0.0f);
    }
    __syncthreads();
    if (t == 0) {
        float sc = b2[0];
        #pragma unroll
        for (int j = 0; j < HID; j++) sc = fmaf(hsh[j], W2[j], sc);
        out_score[0] = sc;
    }
}

// =====================================================================
// Inputs (metadata order): H, TPL, Wv, bv, Wu, bu, Ww, bw, W1, b1, W2, b2
// Output: [score, alpha[0..N-1]]
// =====================================================================
extern "C" void kernel_launch(void* const* d_in, const int* in_sizes, int n_in,
                              void* d_out, int out_size)
{
    const float* H   = (const float*)d_in[0];
    const float* TPL = (const float*)d_in[1];
    const float* Wv  = (const float*)d_in[2];
    const float* bv  = (const float*)d_in[3];
    const float* Wu  = (const float*)d_in[4];
    const float* bu  = (const float*)d_in[5];
    const float* Ww  = (const float*)d_in[6];
    const float* bw  = (const float*)d_in[7];
    const float* W1  = (const float*)d_in[8];
    const float* b1  = (const float*)d_in[9];
    const float* W2  = (const float*)d_in[10];
    const float* b2  = (const float*)d_in[11];
    float* out = (float*)d_out;

    const int n = in_sizes[0] / D;   // 1,000,000

    k1_logits<<<NB, T1>>>((const float4*)H, n, Wv, bv, Wu, bu, Ww, bw);
    k2_stats<<<1, 256>>>();
    k3_alpha_B<<<NB, T1>>>((const float4*)H, n, out + 1);
    k4_head<<<1, 1024>>>(TPL, W1, b1, W2, b2, out);
}